// round 1
// baseline (speedup 1.0000x reference)
#include <cuda_runtime.h>

#define NN   2048
#define MEM  1024
#define NCTA 128
#define TPB  256

// Persistent device scratch (allocation-free rule: __device__ globals).
__device__ __align__(16) float g_Gx[NN * 5 * MEM];   // 40 MB input projection
__device__ __align__(16) float g_h[MEM];             // recurrent hidden broadcast
__device__ __align__(16) float g_v[MEM];             // z*tanh(c) broadcast
__device__ unsigned int g_bar;                       // grid barrier counter

__device__ __forceinline__ float sigf(float x) { return 1.0f / (1.0f + expf(-x)); }

__device__ __forceinline__ float warpSum(float v) {
#pragma unroll
    for (int o = 16; o > 0; o >>= 1) v += __shfl_down_sync(0xffffffffu, v, o);
    return v;
}

// Monotonic-counter grid barrier. Valid because all NCTA CTAs are co-resident
// (168KB smem -> 1 CTA/SM, NCTA=128 <= 148 SMs). g_bar is reset to 0 by the
// GEMM kernel that precedes this kernel in every launch (graph replay safe).
__device__ __forceinline__ void grid_barrier(unsigned int target) {
    __syncthreads();
    if (threadIdx.x == 0) {
        __threadfence();                       // release all this CTA's writes
        atomicAdd(&g_bar, 1u);
        volatile unsigned int* p = &g_bar;     // ld.volatile.global (L2, no L1)
        while (*p < target) { }
        __threadfence();                       // acquire
    }
    __syncthreads();
}

// ---------------------------------------------------------------------------
// Kernel 1: Gx = inputs @ Wx + bx   (2048 x 1024) @ (1024 x 5120)
// Classic 128x128x8 SGEMM, 256 threads, 8x8 per-thread tile.
// ---------------------------------------------------------------------------
__global__ void __launch_bounds__(256) gemm_gx_kernel(
    const float* __restrict__ A,   // inputs (2048,1024)
    const float* __restrict__ B,   // Wx (1024,5120)
    const float* __restrict__ bx)  // (5120,)
{
    if (blockIdx.x == 0 && blockIdx.y == 0 && threadIdx.x == 0) g_bar = 0u;

    __shared__ float As[8][128];
    __shared__ float Bs[8][132];   // +4 pad keeps float4 alignment, kills conflicts

    const int tid  = threadIdx.x;
    const int tx   = tid & 15;          // 0..15 (N direction)
    const int ty   = tid >> 4;          // 0..15 (M direction)
    const int arow = tid >> 1;          // 0..127
    const int akc  = (tid & 1) << 2;    // 0 or 4
    const int bkr  = tid >> 5;          // 0..7
    const int bcol = (tid & 31) << 2;   // 0..124

    const int m0 = blockIdx.y << 7;
    const int n0 = blockIdx.x << 7;

    const float* Aptr = A + (m0 + arow) * 1024 + akc;
    const float* Bptr = B + bkr * 5120 + n0 + bcol;

    float acc[8][8];
#pragma unroll
    for (int i = 0; i < 8; ++i)
#pragma unroll
        for (int j = 0; j < 8; ++j) acc[i][j] = 0.0f;

    for (int kt = 0; kt < 1024; kt += 8) {
        const float4 av = __ldg((const float4*)(Aptr + kt));
        const float4 bv = __ldg((const float4*)(Bptr + kt * 5120));
        As[akc + 0][arow] = av.x;
        As[akc + 1][arow] = av.y;
        As[akc + 2][arow] = av.z;
        As[akc + 3][arow] = av.w;
        *(float4*)&Bs[bkr][bcol] = bv;
        __syncthreads();

#pragma unroll
        for (int k = 0; k < 8; ++k) {
            float ar[8], br[8];
            *(float4*)(ar)     = *(const float4*)&As[k][ty * 8];
            *(float4*)(ar + 4) = *(const float4*)&As[k][ty * 8 + 4];
            *(float4*)(br)     = *(const float4*)&Bs[k][tx * 8];
            *(float4*)(br + 4) = *(const float4*)&Bs[k][tx * 8 + 4];
#pragma unroll
            for (int i = 0; i < 8; ++i)
#pragma unroll
                for (int j = 0; j < 8; ++j) acc[i][j] += ar[i] * br[j];
        }
        __syncthreads();
    }

    const int crow = m0 + ty * 8;
    const int ccol = n0 + tx * 8;
    float bxv[8];
    *(float4*)(bxv)     = __ldg((const float4*)&bx[ccol]);
    *(float4*)(bxv + 4) = __ldg((const float4*)&bx[ccol + 4]);
#pragma unroll
    for (int i = 0; i < 8; ++i) {
        float4 c0 = make_float4(acc[i][0] + bxv[0], acc[i][1] + bxv[1],
                                acc[i][2] + bxv[2], acc[i][3] + bxv[3]);
        float4 c1 = make_float4(acc[i][4] + bxv[4], acc[i][5] + bxv[5],
                                acc[i][6] + bxv[6], acc[i][7] + bxv[7]);
        *(float4*)&g_Gx[(size_t)(crow + i) * 5120 + ccol]     = c0;
        *(float4*)&g_Gx[(size_t)(crow + i) * 5120 + ccol + 4] = c1;
    }
}

// ---------------------------------------------------------------------------
// Kernel 2: persistent sequential scan. 128 CTAs, CTA s owns state dims
// m = 8s..8s+7 and keeps its Wh/Wum columns in SMEM for all 2048 steps.
// ---------------------------------------------------------------------------
__global__ void __launch_bounds__(TPB, 1) scan_kernel(
    const float* __restrict__ Wh,  const float* __restrict__ bh,
    const float* __restrict__ Wum, const float* __restrict__ bum,
    const float* __restrict__ pic, const float* __restrict__ pfc,
    const float* __restrict__ poc, const float* __restrict__ pzc,
    float* __restrict__ out)
{
    extern __shared__ float smf[];
    float* whs  = smf;                  // 32*1024 : Wh columns, [c][k], c = g*8+j
    float* wums = smf + 32 * MEM;       //  8*1024 : Wum columns, [j][k]
    float* hv   = wums + 8 * MEM;       //  1024   : h (phase 1) / v (phase 2)
    float* ghs  = hv + MEM;             //  32     : per-column dot results

    const int tid  = threadIdx.x;
    const int m0   = blockIdx.x * 8;
    const int w    = tid >> 5;
    const int lane = tid & 31;

    // ---- stage weights into SMEM (one-time per launch) ----
#pragma unroll 1
    for (int c = 0; c < 32; ++c) {
        const int col = (c >> 3) * MEM + m0 + (c & 7);   // gate*1024 + m
        for (int k = tid; k < MEM; k += TPB)
            whs[c * MEM + k] = __ldg(&Wh[k * (4 * MEM) + col]);
    }
#pragma unroll 1
    for (int c = 0; c < 8; ++c) {
        const int col = m0 + c;
        for (int k = tid; k < MEM; k += TPB)
            wums[c * MEM + k] = __ldg(&Wum[k * MEM + col]);
    }

    // per-dim constants live in registers of threads 0..7
    float bh_i = 0, bh_o = 0, bh_f = 0, bh_z = 0, bum_v = 0;
    float pic_v = 0, pfc_v = 0, poc_v = 0, pzc_v = 0;
    if (tid < 8) {
        const int m = m0 + tid;
        bh_i = bh[m];           bh_o = bh[MEM + m];
        bh_f = bh[2 * MEM + m]; bh_z = bh[3 * MEM + m];
        bum_v = bum[m];
        pic_v = pic[m]; pfc_v = pfc[m]; poc_v = poc[m]; pzc_v = pzc[m];
    }
    float cp = 0.0f, iv = 0.0f, fv = 0.0f, opre = 0.0f, gxu = 0.0f;
    float hmx = -3.402823466e38f;

    const float4* w4a = (const float4*)(whs + (4 * w + 0) * MEM);
    const float4* w4b = (const float4*)(whs + (4 * w + 1) * MEM);
    const float4* w4c = (const float4*)(whs + (4 * w + 2) * MEM);
    const float4* w4d = (const float4*)(whs + (4 * w + 3) * MEM);
    const float4* wm4 = (const float4*)(wums + w * MEM);
    float4* hv4 = (float4*)hv;

    unsigned int target = 0;
    __syncthreads();

#pragma unroll 1
    for (int t = 0; t < NN; ++t) {
        // ---- phase 1: gh = h @ Wh (our 32 columns), gates i/f/z, emit v ----
        if (t == 0) hv4[tid] = make_float4(0.f, 0.f, 0.f, 0.f);
        else        hv4[tid] = __ldcg(((const float4*)g_h) + tid);   // L2 coherent
        __syncthreads();

        float gxi = 0, gxo = 0, gxf = 0, gxz = 0;
        if (tid < 8) {   // prefetch this node's Gx early; latency covered by dots
            const float* gx = g_Gx + (size_t)t * (5 * MEM) + m0 + tid;
            gxi = __ldg(gx);
            gxo = __ldg(gx + MEM);
            gxf = __ldg(gx + 2 * MEM);
            gxz = __ldg(gx + 3 * MEM);
            gxu = __ldg(gx + 4 * MEM);
        }

        float a0 = 0, a1 = 0, a2 = 0, a3 = 0;
#pragma unroll
        for (int i = 0; i < 8; ++i) {
            const int idx = i * 32 + lane;
            const float4 h4 = hv4[idx];
            float4 x;
            x = w4a[idx]; a0 += h4.x * x.x + h4.y * x.y + h4.z * x.z + h4.w * x.w;
            x = w4b[idx]; a1 += h4.x * x.x + h4.y * x.y + h4.z * x.z + h4.w * x.w;
            x = w4c[idx]; a2 += h4.x * x.x + h4.y * x.y + h4.z * x.z + h4.w * x.w;
            x = w4d[idx]; a3 += h4.x * x.x + h4.y * x.y + h4.z * x.z + h4.w * x.w;
        }
        a0 = warpSum(a0); a1 = warpSum(a1); a2 = warpSum(a2); a3 = warpSum(a3);
        if (lane == 0) {
            ghs[4 * w + 0] = a0; ghs[4 * w + 1] = a1;
            ghs[4 * w + 2] = a2; ghs[4 * w + 3] = a3;
        }
        __syncthreads();

        if (tid < 8) {
            const float ih = ghs[tid]      + bh_i;
            const float oh = ghs[8 + tid]  + bh_o;
            const float fh = ghs[16 + tid] + bh_f;
            const float zh = ghs[24 + tid] + bh_z;
            iv   = sigf(gxi + ih + pic_v * cp);
            fv   = sigf(gxf + fh + pfc_v * cp);
            const float zv = sigf(gxz + zh + pzc_v * cp);
            opre = gxo + oh;
            __stcg(&g_v[m0 + tid], zv * tanhf(cp));
        }
        target += NCTA;
        grid_barrier(target);

        // ---- phase 2: u = tanh(gux + v @ Wum + bum); c, o, h; emit h ----
        hv4[tid] = __ldcg(((const float4*)g_v) + tid);
        __syncthreads();

        float b0 = 0.0f;
#pragma unroll
        for (int i = 0; i < 8; ++i) {
            const int idx = i * 32 + lane;
            const float4 v4 = hv4[idx];
            const float4 x  = wm4[idx];
            b0 += v4.x * x.x + v4.y * x.y + v4.z * x.z + v4.w * x.w;
        }
        b0 = warpSum(b0);
        if (lane == 0) ghs[w] = b0;
        __syncthreads();

        if (tid < 8) {
            const float u = tanhf(gxu + ghs[tid] + bum_v);
            const float c = iv * u + fv * cp;
            const float o = sigf(opre + poc_v * c);
            const float h = o * tanhf(c);
            cp  = c;
            hmx = fmaxf(hmx, h);
            __stcg(&g_h[m0 + tid], h);
        }
        target += NCTA;
        grid_barrier(target);
    }

    if (tid < 8) out[m0 + tid] = hmx;
}

// ---------------------------------------------------------------------------
extern "C" void kernel_launch(void* const* d_in, const int* in_sizes, int n_in,
                              void* d_out, int out_size) {
    const float* inputs = (const float*)d_in[0];
    const float* Wx     = (const float*)d_in[1];
    const float* bx     = (const float*)d_in[2];
    const float* Wh     = (const float*)d_in[3];
    const float* bh     = (const float*)d_in[4];
    const float* Wum    = (const float*)d_in[5];
    const float* bum    = (const float*)d_in[6];
    const float* pic    = (const float*)d_in[7];
    const float* pfc    = (const float*)d_in[8];
    const float* poc    = (const float*)d_in[9];
    const float* pzc    = (const float*)d_in[10];
    float* out = (float*)d_out;

    const int smem_bytes = (32 * MEM + 8 * MEM + MEM + 32) * (int)sizeof(float);
    cudaFuncSetAttribute(scan_kernel,
                         cudaFuncAttributeMaxDynamicSharedMemorySize, smem_bytes);

    dim3 gg(5120 / 128, 2048 / 128);
    gemm_gx_kernel<<<gg, 256>>>(inputs, Wx, bx);
    scan_kernel<<<NCTA, TPB, smem_bytes>>>(Wh, bh, Wum, bum,
                                           pic, pfc, poc, pzc, out);
}